// round 1
// baseline (speedup 1.0000x reference)
#include <cuda_runtime.h>
#include <cuda_bf16.h>
#include <math.h>

// TemporalAttention collapses: y = einsum('TNS,BNH->BNH', softmax(attn), v)
// sums attn over T and S entirely; softmax rows sum to 1, so y = N * v.
// Only the Wv/Wo projection, gate MLP and mixer MLP survive.

#define HID 128
#define ROWS 8
#define NNODES 1024

// One GEMM-stage accumulator: acc[r] += sum_k sT[k][r] * W[k*HID + c]
__device__ __forceinline__ void gemm128(const float* __restrict__ W,
                                        const float (*__restrict__ sT)[ROWS],
                                        int c, float acc[ROWS]) {
#pragma unroll 8
    for (int k = 0; k < HID; k++) {
        float w = W[k * HID + c];
        float4 a0 = *(const float4*)(&sT[k][0]);
        float4 a1 = *(const float4*)(&sT[k][4]);
        acc[0] += a0.x * w; acc[1] += a0.y * w;
        acc[2] += a0.z * w; acc[3] += a0.w * w;
        acc[4] += a1.x * w; acc[5] += a1.y * w;
        acc[6] += a1.z * w; acc[7] += a1.w * w;
    }
}

extern "C" __global__ void __launch_bounds__(128, 1)
temporal_attn_fused(const float* __restrict__ h_prev,
                    const float* __restrict__ h_pred,
                    const float* __restrict__ Wv, const float* __restrict__ bv,
                    const float* __restrict__ Wo, const float* __restrict__ bo,
                    const float* __restrict__ gW1, const float* __restrict__ gb1,
                    const float* __restrict__ gW2, const float* __restrict__ gb2,
                    const float* __restrict__ mW1, const float* __restrict__ mb1,
                    const float* __restrict__ mW2, const float* __restrict__ mb2,
                    float* __restrict__ out) {
    __shared__ float hpT[HID][ROWS];   // h_pred rows, transposed [k][r]
    __shared__ float hvT[HID][ROWS];   // h_prev rows, transposed
    __shared__ float tmpT[HID][ROWS];  // v / g1 / m1 scratch, transposed
    __shared__ float hcT[HID][ROWS];   // h_corr, transposed

    const int c = threadIdx.x;           // output column owned by this thread
    const int r0 = blockIdx.x * ROWS;    // first row of this CTA's tile

    // Stage inputs transposed: thread c supplies column c of each row.
#pragma unroll
    for (int r = 0; r < ROWS; r++) {
        hpT[c][r] = h_pred[(r0 + r) * HID + c];
        hvT[c][r] = h_prev[(r0 + r) * HID + c];
    }
    __syncthreads();

    float acc[ROWS], outr[ROWS], hc[ROWS];

    // ---- Stage 1: v = h_pred @ Wv + bv  -> tmpT ----
    {
        float b = bv[c];
#pragma unroll
        for (int r = 0; r < ROWS; r++) acc[r] = b;
    }
    gemm128(Wv, hpT, c, acc);
#pragma unroll
    for (int r = 0; r < ROWS; r++) tmpT[c][r] = acc[r];
    __syncthreads();

    // ---- Stage 2: out = N * (v @ Wo) + bo  (kept in registers) ----
#pragma unroll
    for (int r = 0; r < ROWS; r++) acc[r] = 0.0f;
    gemm128(Wo, tmpT, c, acc);
    {
        float b = bo[c];
#pragma unroll
        for (int r = 0; r < ROWS; r++) outr[r] = (float)NNODES * acc[r] + b;
    }
    __syncthreads();  // everyone done reading tmpT(v) before it is reused

    // ---- Stage 3: g1 = silu(h_pred@gW1[:128] + h_prev@gW1[128:] + gb1) -> tmpT ----
    {
        float b = gb1[c];
#pragma unroll
        for (int r = 0; r < ROWS; r++) acc[r] = b;
    }
    gemm128(gW1, hpT, c, acc);
    gemm128(gW1 + HID * HID, hvT, c, acc);
#pragma unroll
    for (int r = 0; r < ROWS; r++) {
        float x = acc[r];
        tmpT[c][r] = x / (1.0f + expf(-x));  // silu
    }
    __syncthreads();

    // ---- Stage 4: gate = sigmoid(g1 @ gW2 + gb2); h_corr = h_prev + gate*out -> hcT ----
    {
        float b = gb2[c];
#pragma unroll
        for (int r = 0; r < ROWS; r++) acc[r] = b;
    }
    gemm128(gW2, tmpT, c, acc);
#pragma unroll
    for (int r = 0; r < ROWS; r++) {
        float g = 1.0f / (1.0f + expf(-acc[r]));
        hc[r] = hvT[c][r] + g * outr[r];
        hcT[c][r] = hc[r];
    }
    __syncthreads();  // hcT visible; also fences stage-4 tmpT reads

    // ---- Stage 5: m1 = relu(h_corr@mW1[:128] + h_prev@mW1[128:] + mb1) -> tmpT ----
    {
        float b = mb1[c];
#pragma unroll
        for (int r = 0; r < ROWS; r++) acc[r] = b;
    }
    gemm128(mW1, hcT, c, acc);
    gemm128(mW1 + HID * HID, hvT, c, acc);
#pragma unroll
    for (int r = 0; r < ROWS; r++) tmpT[c][r] = fmaxf(acc[r], 0.0f);
    __syncthreads();

    // ---- Stage 6: mixed = h_corr + m1 @ mW2 + mb2 ----
    {
        float b = mb2[c];
#pragma unroll
        for (int r = 0; r < ROWS; r++) acc[r] = b;
    }
    gemm128(mW2, tmpT, c, acc);
#pragma unroll
    for (int r = 0; r < ROWS; r++) {
        out[(r0 + r) * HID + c] = hc[r] + acc[r];
    }
}

extern "C" void kernel_launch(void* const* d_in, const int* in_sizes, int n_in,
                              void* d_out, int out_size) {
    // metadata order: h_prev, h_pred, adj_rows, adj_cols, Wq, bq, Wk, bk,
    //                 Wv, bv, Wo, bo, gW1, gb1, gW2, gb2, mW1, mb1, mW2, mb2
    const float* h_prev = (const float*)d_in[0];
    const float* h_pred = (const float*)d_in[1];
    // d_in[2..7] (adjacency, Wq/bq/Wk/bk) are algebraically dead — see header note.
    const float* Wv  = (const float*)d_in[8];
    const float* bv  = (const float*)d_in[9];
    const float* Wo  = (const float*)d_in[10];
    const float* bo  = (const float*)d_in[11];
    const float* gW1 = (const float*)d_in[12];
    const float* gb1 = (const float*)d_in[13];
    const float* gW2 = (const float*)d_in[14];
    const float* gb2 = (const float*)d_in[15];
    const float* mW1 = (const float*)d_in[16];
    const float* mb1 = (const float*)d_in[17];
    const float* mW2 = (const float*)d_in[18];
    const float* mb2 = (const float*)d_in[19];
    float* out = (float*)d_out;

    temporal_attn_fused<<<NNODES / ROWS, HID>>>(
        h_prev, h_pred, Wv, bv, Wo, bo,
        gW1, gb1, gW2, gb2, mW1, mb1, mW2, mb2, out);
}

// round 2
// speedup vs baseline: 1.8431x; 1.8431x over previous
#include <cuda_runtime.h>
#include <cuda_bf16.h>
#include <math.h>

// Attention path collapses (softmax rows sum to 1; T,S fully contracted):
//   y = 1024 * (h_pred @ Wv + bv)
// Only Wv/Wo projection + gate MLP + mixer MLP survive.
//
// R1: latency-bound fix — 512 threads/CTA with 4-way k-slicing (16 warps/SM
// instead of 4) + packed fma.rn.f32x2 to halve fma-pipe instruction count.

#define HID 128
#define ROWS 8
#define SLICES 4
#define KS (HID / SLICES)   // 32 k-values per slice
#define NNODES 1024
#define NTHREADS (HID * SLICES)  // 512

typedef unsigned long long u64;

__device__ __forceinline__ u64 fma2(u64 a, u64 b, u64 c) {
    u64 d;
    asm("fma.rn.f32x2 %0, %1, %2, %3;" : "=l"(d) : "l"(a), "l"(b), "l"(c));
    return d;
}

// Partial GEMM over this slice's k-range:
//   acc(pairs of rows) += sT[k][0..7] * W[k*HID + c]
__device__ __forceinline__ void gemm_slice(const float* __restrict__ W,
                                           const float (*__restrict__ sT)[ROWS],
                                           int c, int k0, u64 acc[4]) {
#pragma unroll 8
    for (int k = k0; k < k0 + KS; k++) {
        float w = W[k * HID + c];
        u64 ww;
        asm("mov.b64 %0, {%1, %1};" : "=l"(ww) : "f"(w));
        const u64* a = (const u64*)(&sT[k][0]);  // 4x float2 (8 rows)
        acc[0] = fma2(a[0], ww, acc[0]);
        acc[1] = fma2(a[1], ww, acc[1]);
        acc[2] = fma2(a[2], ww, acc[2]);
        acc[3] = fma2(a[3], ww, acc[3]);
    }
}

extern "C" __global__ void __launch_bounds__(NTHREADS, 1)
temporal_attn_fused(const float* __restrict__ h_prev,
                    const float* __restrict__ h_pred,
                    const float* __restrict__ Wv, const float* __restrict__ bv,
                    const float* __restrict__ Wo, const float* __restrict__ bo,
                    const float* __restrict__ gW1, const float* __restrict__ gb1,
                    const float* __restrict__ gW2, const float* __restrict__ gb2,
                    const float* __restrict__ mW1, const float* __restrict__ mb1,
                    const float* __restrict__ mW2, const float* __restrict__ mb2,
                    float* __restrict__ out) {
    __shared__ float hpT[HID][ROWS];    // h_pred tile, transposed [k][r]
    __shared__ float hvT[HID][ROWS];    // h_prev tile, transposed
    __shared__ float tmpT[HID][ROWS];   // v / g1 / m1 scratch
    __shared__ float hcT[HID][ROWS];    // h_corr
    __shared__ float outS[HID][ROWS];   // attention-out, then final result
    __shared__ float part[SLICES][HID][ROWS];  // per-slice partials

    const int tid = threadIdx.x;
    const int c = tid & (HID - 1);    // output column
    const int s = tid >> 7;           // k-slice 0..3
    const int k0 = s * KS;
    const int r0 = blockIdx.x * ROWS;

    float* hpF  = (float*)hpT;
    float* hvF  = (float*)hvT;
    float* tmpF = (float*)tmpT;
    float* hcF  = (float*)hcT;
    float* outF = (float*)outS;
    float* pF   = (float*)part;       // pF[s*1024 + p]

    // Stage inputs transposed (coalesced global reads).
#pragma unroll
    for (int j = 0; j < 2; j++) {
        int g = tid + j * NTHREADS;       // 0..1023 within tile
        int r = g >> 7, cc = g & (HID - 1);
        hpT[cc][r] = h_pred[(r0 + r) * HID + cc];
        hvT[cc][r] = h_prev[(r0 + r) * HID + cc];
    }
    __syncthreads();

    u64 acc[4];
    u64* pdst = (u64*)&part[s][c][0];

#define GEMM_ZERO()  { acc[0] = acc[1] = acc[2] = acc[3] = 0ULL; }
#define GEMM_STORE() { pdst[0] = acc[0]; pdst[1] = acc[1]; pdst[2] = acc[2]; pdst[3] = acc[3]; }

    // ---- Stage 1: v = h_pred @ Wv + bv -> tmpT ----
    GEMM_ZERO();
    gemm_slice(Wv, hpT, c, k0, acc);
    GEMM_STORE();
    __syncthreads();
#pragma unroll
    for (int j = 0; j < 2; j++) {
        int p = tid + j * NTHREADS;
        float v = pF[p] + pF[1024 + p] + pF[2048 + p] + pF[3072 + p];
        tmpF[p] = v + bv[p >> 3];
    }
    __syncthreads();

    // ---- Stage 2: out = 1024*(v @ Wo) + bo -> outS ----
    GEMM_ZERO();
    gemm_slice(Wo, tmpT, c, k0, acc);
    GEMM_STORE();
    __syncthreads();
#pragma unroll
    for (int j = 0; j < 2; j++) {
        int p = tid + j * NTHREADS;
        float v = pF[p] + pF[1024 + p] + pF[2048 + p] + pF[3072 + p];
        outF[p] = (float)NNODES * v + bo[p >> 3];
    }
    __syncthreads();

    // ---- Stage 3: g1 = silu(h_pred@gW1_top + h_prev@gW1_bot + gb1) -> tmpT ----
    GEMM_ZERO();
    gemm_slice(gW1, hpT, c, k0, acc);
    gemm_slice(gW1 + HID * HID, hvT, c, k0, acc);
    GEMM_STORE();
    __syncthreads();
#pragma unroll
    for (int j = 0; j < 2; j++) {
        int p = tid + j * NTHREADS;
        float x = pF[p] + pF[1024 + p] + pF[2048 + p] + pF[3072 + p] + gb1[p >> 3];
        tmpF[p] = x / (1.0f + __expf(-x));   // silu
    }
    __syncthreads();

    // ---- Stage 4: gate = sigmoid(g1@gW2 + gb2); h_corr = h_prev + gate*out -> hcT ----
    GEMM_ZERO();
    gemm_slice(gW2, tmpT, c, k0, acc);
    GEMM_STORE();
    __syncthreads();
#pragma unroll
    for (int j = 0; j < 2; j++) {
        int p = tid + j * NTHREADS;
        float x = pF[p] + pF[1024 + p] + pF[2048 + p] + pF[3072 + p] + gb2[p >> 3];
        float g = 1.0f / (1.0f + __expf(-x));
        hcF[p] = hvF[p] + g * outF[p];
    }
    __syncthreads();

    // ---- Stage 5: m1 = relu(h_corr@mW1_top + h_prev@mW1_bot + mb1) -> tmpT ----
    GEMM_ZERO();
    gemm_slice(mW1, hcT, c, k0, acc);
    gemm_slice(mW1 + HID * HID, hvT, c, k0, acc);
    GEMM_STORE();
    __syncthreads();
#pragma unroll
    for (int j = 0; j < 2; j++) {
        int p = tid + j * NTHREADS;
        float x = pF[p] + pF[1024 + p] + pF[2048 + p] + pF[3072 + p] + mb1[p >> 3];
        tmpF[p] = fmaxf(x, 0.0f);
    }
    __syncthreads();

    // ---- Stage 6: mixed = h_corr + m1 @ mW2 + mb2 -> outS, then coalesced store ----
    GEMM_ZERO();
    gemm_slice(mW2, tmpT, c, k0, acc);
    GEMM_STORE();
    __syncthreads();
#pragma unroll
    for (int j = 0; j < 2; j++) {
        int p = tid + j * NTHREADS;
        float v = pF[p] + pF[1024 + p] + pF[2048 + p] + pF[3072 + p] + mb2[p >> 3];
        outF[p] = hcF[p] + v;
    }
    __syncthreads();

    // Coalesced global store: warp-groups own rows, lanes own columns.
#pragma unroll
    for (int j = 0; j < 2; j++) {
        int r = s + j * SLICES;        // rows 0..3 then 4..7
        out[(r0 + r) * HID + c] = outS[c][r];
    }
}

extern "C" void kernel_launch(void* const* d_in, const int* in_sizes, int n_in,
                              void* d_out, int out_size) {
    // metadata order: h_prev, h_pred, adj_rows, adj_cols, Wq, bq, Wk, bk,
    //                 Wv, bv, Wo, bo, gW1, gb1, gW2, gb2, mW1, mb1, mW2, mb2
    const float* h_prev = (const float*)d_in[0];
    const float* h_pred = (const float*)d_in[1];
    // d_in[2..7] (adjacency, Wq/bq/Wk/bk) are algebraically dead.
    const float* Wv  = (const float*)d_in[8];
    const float* bv  = (const float*)d_in[9];
    const float* Wo  = (const float*)d_in[10];
    const float* bo  = (const float*)d_in[11];
    const float* gW1 = (const float*)d_in[12];
    const float* gb1 = (const float*)d_in[13];
    const float* gW2 = (const float*)d_in[14];
    const float* gb2 = (const float*)d_in[15];
    const float* mW1 = (const float*)d_in[16];
    const float* mb1 = (const float*)d_in[17];
    const float* mW2 = (const float*)d_in[18];
    const float* mb2 = (const float*)d_in[19];
    float* out = (float*)d_out;

    temporal_attn_fused<<<NNODES / ROWS, NTHREADS>>>(
        h_prev, h_pred, Wv, bv, Wo, bo,
        gW1, gb1, gW2, gb2, mW1, mb1, mW2, mb2, out);
}